// round 16
// baseline (speedup 1.0000x reference)
#include <cuda_runtime.h>
#include <cuda_fp16.h>
#include <cstdint>

// ---------------------------------------------------------------------------
// TernaryConv2d via implicit GEMM with mma.sync.m16n8k16.f16 (fp32 accum).
//   C[256, 100352] = Wt[256,2304] @ im2col(x_h)[2304, 100352]
// K order k = rr*256 + ci. x pre-quantized fp16 in 3 dw-shifted halo copies
// (pixel-linear, plane stride 3264 = 51*128B).
// R16: BK=32 (72 stages), D=5 ring (wait_group 3 = 96k lookahead), per-stage
// sync. Amortizes the ~98cyc fixed stage cost over 2x tensor work. Inner body
// = two copies of the proven k16 body; everything else byte-identical to R15.
// ---------------------------------------------------------------------------

#define CIN   256
#define COUT  256
#define HW    56
#define PIX   3136
#define KTOT  2304
#define NW    (COUT*KTOT)
#define H2    58
#define CHW2P 3264                       // padded plane stride (halves)
#define NP    (32*PIX)                   // 100352
#define XCOPY (32*CIN*CHW2P)

#define BM 128
#define BN 128
#define BK 32
#define NSTAGE 72
#define D 5                              // ring slots (16KB each)
#define STG_A 8192
#define STG_BYTES 16384
#define SMEM_DYN (D*STG_BYTES)           // 81920

// scratch (device globals)
__device__ __half g_wth[NW];          // fragment-major ternary weights
__device__ __half g_xh[3*XCOPY];      // fp16 x, 3 dw-shifted halo copies
__device__ float  g_partial[256];
__device__ float  g_delta;

// ------------- fused: xtoh (blocks 0..8191) + absmean_part (8192..8447) -----
__global__ void __launch_bounds__(416) fused_pre(const float* __restrict__ x,
                                                 const float* __restrict__ w) {
    const int t = threadIdx.x;

    if (blockIdx.x >= 8192) {
        __shared__ float sm[256];
        const int blk = blockIdx.x - 8192;
        float s = 0.f;
        if (t < 256) {
            int base = blk * 256 + t;
#pragma unroll
            for (int k = 0; k < 9; k++) s += fabsf(w[base + k * 65536]);
            sm[t] = s;
        }
        __syncthreads();
        for (int st = 128; st > 0; st >>= 1) {
            if (t < st) sm[t] += sm[t + st];
            __syncthreads();
        }
        if (t == 0) g_partial[blk] = sm[0];
        return;
    }

    const int bc = blockIdx.x;
    if (t >= H2 * 7) return;
    const int hp = t / 7;
    const int w8 = t - hp * 7;
    const int h  = hp - 1;
    const bool hv = (unsigned)h < (unsigned)HW;
    const float* xr = x + (size_t)bc * PIX + h * HW;

    __half hb[10];
#pragma unroll
    for (int j = 0; j < 10; j++) {
        int ww = w8 * 8 - 1 + j;
        float v = (hv && (unsigned)ww < (unsigned)HW) ? xr[ww] : 0.f;
        hb[j] = __float2half_rn(v);
    }
    uint32_t p[5];
#pragma unroll
    for (int g = 0; g < 5; g++) {
        __half2 h2 = __halves2half2(hb[2 * g], hb[2 * g + 1]);
        p[g] = *reinterpret_cast<uint32_t*>(&h2);
    }
    uint32_t q[4];
#pragma unroll
    for (int g = 0; g < 4; g++)
        asm("prmt.b32 %0, %1, %2, 0x5432;" : "=r"(q[g]) : "r"(p[g]), "r"(p[g + 1]));

    const size_t base = (size_t)bc * CHW2P + hp * HW + w8 * 8;
    uint4* o0 = reinterpret_cast<uint4*>(g_xh + base);
    uint4* o1 = reinterpret_cast<uint4*>(g_xh + base + (size_t)XCOPY);
    uint4* o2 = reinterpret_cast<uint4*>(g_xh + base + 2 * (size_t)XCOPY);
    *o0 = make_uint4(p[0], p[1], p[2], p[3]);
    *o1 = make_uint4(q[0], q[1], q[2], q[3]);
    *o2 = make_uint4(p[1], p[2], p[3], p[4]);
}

__global__ void absmean_final() {
    __shared__ float sm[256];
    int tid = threadIdx.x;
    sm[tid] = g_partial[tid]; __syncthreads();
    for (int st = 128; st > 0; st >>= 1) {
        if (tid < st) sm[tid] += sm[tid + st];
        __syncthreads();
    }
    if (tid == 0) g_delta = 0.7f * sm[0] / (float)NW;
}

// -------- ternarize + pack into mma-fragment-major fp16 layout -------------
// per k16 sub-stage (2048 halves): [m16(8)][lane(32)][aidx(4)][hp(2)]
__global__ void ternarize(const float* __restrict__ w) {
    int idx = blockIdx.x * 256 + threadIdx.x;
    float d = g_delta, v = w[idx];
    float t = (v > d) ? 1.f : ((v < -d) ? -1.f : 0.f);
    int co  = idx / KTOT;
    int rem = idx - co * KTOT;
    int ci  = rem / 9;
    int rr  = rem - ci * 9;
    int k   = rr * 256 + ci;
    int s   = k >> 4, kin = k & 15;          // k16 sub-stage 0..143
    int bm  = co >> 7, m = co & 127, m16 = m >> 4, mi = m & 15;
    int lane = ((mi & 7) << 2) | ((kin >> 1) & 3);
    int aidx = ((kin >> 3) << 1) + (mi >> 3);
    int hp   = kin & 1;
    g_wth[(((size_t)bm * 144 + s) * 8 + m16) * 256 + lane * 8 + aidx * 2 + hp]
        = __float2half_rn(t);
}

// ------------------------------ PTX helpers --------------------------------
__device__ __forceinline__ uint32_t smem_u32(const void* p) {
    uint32_t a;
    asm("{ .reg .u64 t; cvta.to.shared.u64 t, %1; cvt.u32.u64 %0, t; }"
        : "=r"(a) : "l"(p));
    return a;
}
__device__ __forceinline__ void cp16cg(uint32_t dst, const void* src) {
    asm volatile("cp.async.cg.shared.global [%0], [%1], 16;\n" :: "r"(dst), "l"(src));
}
__device__ __forceinline__ void lds128(uint32_t* a, uint32_t addr) {
    asm volatile("ld.shared.v4.b32 {%0,%1,%2,%3}, [%4];"
                 : "=r"(a[0]), "=r"(a[1]), "=r"(a[2]), "=r"(a[3]) : "r"(addr));
}
__device__ __forceinline__ void ldsm4t(uint32_t& b0, uint32_t& b1,
                                       uint32_t& b2, uint32_t& b3, uint32_t addr) {
    asm volatile("ldmatrix.sync.aligned.m8n8.x4.trans.shared.b16 {%0,%1,%2,%3}, [%4];"
                 : "=r"(b0), "=r"(b1), "=r"(b2), "=r"(b3) : "r"(addr));
}
__device__ __forceinline__ void mma16816(float* c, const uint32_t* a,
                                         uint32_t b0, uint32_t b1) {
    asm volatile(
        "mma.sync.aligned.m16n8k16.row.col.f32.f16.f16.f32 "
        "{%0,%1,%2,%3}, {%4,%5,%6,%7}, {%8,%9}, {%0,%1,%2,%3};\n"
        : "+f"(c[0]), "+f"(c[1]), "+f"(c[2]), "+f"(c[3])
        : "r"(a[0]), "r"(a[1]), "r"(a[2]), "r"(a[3]), "r"(b0), "r"(b1));
}
__device__ __forceinline__ void stg64cs(void* p, float x, float y) {
    asm volatile("st.global.cs.v2.f32 [%0], {%1,%2};"
                 :: "l"(p), "f"(x), "f"(y) : "memory");
}

// --------------------------------- main GEMM -------------------------------
__global__ void __launch_bounds__(256, 2)
conv_hmma(const float* __restrict__ alpha, const float* __restrict__ bias,
          float* __restrict__ out)
{
    extern __shared__ char smem[];
    const uint32_t sb0 = smem_u32(smem);
    const int tid  = threadIdx.x;
    const int lane = tid & 31;
    const int warp = tid >> 5;
    const int bm   = blockIdx.x;           // 2 along x: B-tile sharers adjacent
    const int bn0  = blockIdx.y * BN;

    // ---- producer constants ----
    const int kk = tid >> 4;               // B k-row 0..15 (and kk+16)
    const int c0 = (tid & 15) << 3;        // col chunk
    const int nc = bn0 + c0;
    const int pb = nc / PIX;
    const int pp = nc - pb * PIX;
    const __half* pbase = g_xh + (size_t)(pb * CIN) * CHW2P + pp;
    const uint32_t dstB = (uint32_t)((STG_A + (kk << 8) + (c0 << 1)) ^ ((kk & 7) << 4));
    const uint32_t dstA = (uint32_t)(tid << 4);
    const __half* asrc  = g_wth + (size_t)bm * (144 * 2048) + tid * 8;

    // ---- consumer constants (offsets relative to k16 sub-block) ----
    const uint32_t aoff0 = (uint32_t)((((warp & 3) * 2) << 9) + (lane << 4));
    const uint32_t aoff1 = aoff0 + 512;
    const int t4 = lane >> 3, r = lane & 7;
    const int kt  = (t4 & 1) << 3;
    const int ctb = ((warp >> 2) << 6) + ((t4 >> 1) << 3);
    uint32_t boff[4];
#pragma unroll
    for (int g = 0; g < 4; g++)
        boff[g] = (uint32_t)(((((kt + r) << 8) + ((ctb + (g << 4)) << 1)))
                             ^ (r << 4));

    float acc[2][8][4];
#pragma unroll
    for (int i = 0; i < 2; i++)
#pragma unroll
        for (int j = 0; j < 8; j++)
#pragma unroll
            for (int q = 0; q < 4; q++) acc[i][j][q] = 0.f;

    auto fill = [&](int t, int sl) {
        const uint32_t sb = sb0 + (uint32_t)sl * STG_BYTES;
        // A: two k16 fragment blocks (4KB each)
        cp16cg(sb + dstA,        asrc + (size_t)t * 4096);
        cp16cg(sb + dstA + 4096, asrc + (size_t)t * 4096 + 2048);
        // B: rows kk and kk+16; stage t: rr = t>>3, ci0 = (t&7)*32
        int rr  = t >> 3;
        int ci  = ((t & 7) << 5) + kk;
        int q   = rr / 3;
        int dwp = rr - q * 3;
        const __half* src = pbase + (size_t)dwp * XCOPY
                          + (size_t)ci * CHW2P + q * HW;
        cp16cg(sb + dstB,        src);
        cp16cg(sb + dstB + 4096, src + 16 * CHW2P);
    };

    // ---- prologue: stages 0..3 in flight (slots 0..3) ----
#pragma unroll
    for (int p = 0; p < D - 1; p++) {
        fill(p, p);
        asm volatile("cp.async.commit_group;" ::: "memory");
    }

    // ---- main loop ----
    int sl = 0;                            // slot of stage s
#pragma unroll 1
    for (int s = 0; s < NSTAGE; s++) {
        asm volatile("cp.async.wait_group %0;" :: "n"(D - 2) : "memory");
        __syncthreads();                   // stage s visible; slot (s-1)%D free
        {
            int slf = sl - 1; if (slf < 0) slf += D;
            if (s + D - 1 < NSTAGE) fill(s + D - 1, slf);
            asm volatile("cp.async.commit_group;" ::: "memory");
        }

        const uint32_t st = sb0 + (uint32_t)sl * STG_BYTES;
#pragma unroll
        for (int k2 = 0; k2 < 2; k2++) {
            const uint32_t ab = st + (uint32_t)(k2 << 12);
            const uint32_t bb = st + STG_A + (uint32_t)(k2 << 12);
            uint32_t a0[4], a1[4];
            lds128(a0, ab + aoff0);
            lds128(a1, ab + aoff1);
#pragma unroll
            for (int g = 0; g < 4; g++) {
                uint32_t b0, b1, b2, b3;
                ldsm4t(b0, b1, b2, b3, bb + boff[g]);
                mma16816(acc[0][2 * g],     a0, b0, b1);
                mma16816(acc[1][2 * g],     a1, b0, b1);
                mma16816(acc[0][2 * g + 1], a0, b2, b3);
                mma16816(acc[1][2 * g + 1], a1, b2, b3);
            }
        }
        sl += 1; if (sl == D) sl = 0;
    }

    // ------------------------------ epilogue -------------------------------
    const float al  = alpha[0];
    const int wm0 = (warp & 3) << 5;
    const int wn0 = (warp >> 2) << 6;
#pragma unroll
    for (int mt = 0; mt < 2; mt++) {
        int co = bm * BM + wm0 + (mt << 4) + (lane >> 2);
        float bi0 = bias[co];
        float bi8 = bias[co + 8];
#pragma unroll
        for (int nt = 0; nt < 8; nt++) {
            int n = bn0 + wn0 + (nt << 3) + ((lane & 3) << 1);
            int bimg = n / PIX;
            int hw = n - bimg * PIX;
            size_t o = ((size_t)(bimg * COUT + co)) * PIX + hw;
            stg64cs(out + o,           al * acc[mt][nt][0] + bi0,
                                       al * acc[mt][nt][1] + bi0);
            stg64cs(out + o + 8 * PIX, al * acc[mt][nt][2] + bi8,
                                       al * acc[mt][nt][3] + bi8);
        }
    }
}

// ------------------------------- launcher -----------------------------------
extern "C" void kernel_launch(void* const* d_in, const int* in_sizes, int n_in,
                              void* d_out, int out_size) {
    const float* x     = (const float*)d_in[0];
    const float* w     = (const float*)d_in[1];
    const float* alpha = (const float*)d_in[2];
    const float* bias  = (const float*)d_in[3];
    float* out = (float*)d_out;

    cudaFuncSetAttribute(conv_hmma, cudaFuncAttributeMaxDynamicSharedMemorySize,
                         SMEM_DYN);

    fused_pre<<<8192 + 256, 416>>>(x, w);   // xtoh || absmean_part
    absmean_final<<<1, 256>>>();
    ternarize<<<NW / 256, 256>>>(w);

    dim3 grid(COUT / BM, NP / BN);   // (2, 784): B-tile sharers adjacent
    conv_hmma<<<grid, 256, SMEM_DYN>>>(alpha, bias, out);
}

// round 17
// speedup vs baseline: 1.0161x; 1.0161x over previous
#include <cuda_runtime.h>
#include <cuda_fp16.h>
#include <cstdint>

// ---------------------------------------------------------------------------
// TernaryConv2d via implicit GEMM with mma.sync.m16n8k16.f16 (fp32 accum).
//   C[256, 100352] = Wt[256,2304] @ im2col(x_h)[2304, 100352]
// K order k = rr*256 + ci. x pre-quantized fp16 in 3 dw-shifted halo copies
// (pixel-linear, plane stride 3264 = 51*128B). BK=16, D=8 cp.async ring,
// per-stage sync (R15 engine = measured optimum).
// R17: PERSISTENT CTAs (grid 296 = 2/SM x 148, tile stride 296). bm fixed per
// CTA; NSTAGE%D==0 lets the cp.async ring run seamlessly across tiles: fills
// at s>=137 target the next tile, covering prologue latency and epilogue.
// ---------------------------------------------------------------------------

#define CIN   256
#define COUT  256
#define HW    56
#define PIX   3136
#define KTOT  2304
#define NW    (COUT*KTOT)
#define H2    58
#define CHW2P 3264                       // padded plane stride (halves)
#define NP    (32*PIX)                   // 100352
#define XCOPY (32*CIN*CHW2P)

#define BM 128
#define BN 128
#define BK 16
#define NSTAGE 144
#define D 8
#define STG_A 4096
#define STG_BYTES 8192
#define SMEM_DYN (D*STG_BYTES)           // 65536
#define NTILES 1568                      // (COUT/BM)*(NP/BN)
#define TSTEP  296                       // persistent CTAs

// scratch (device globals)
__device__ __half g_wth[NW];          // fragment-major ternary weights
__device__ __half g_xh[3*XCOPY];      // fp16 x, 3 dw-shifted halo copies
__device__ float  g_partial[256];
__device__ float  g_delta;

// ------------- fused: xtoh (blocks 0..8191) + absmean_part (8192..8447) -----
__global__ void __launch_bounds__(416) fused_pre(const float* __restrict__ x,
                                                 const float* __restrict__ w) {
    const int t = threadIdx.x;

    if (blockIdx.x >= 8192) {
        __shared__ float sm[256];
        const int blk = blockIdx.x - 8192;
        float s = 0.f;
        if (t < 256) {
            int base = blk * 256 + t;
#pragma unroll
            for (int k = 0; k < 9; k++) s += fabsf(w[base + k * 65536]);
            sm[t] = s;
        }
        __syncthreads();
        for (int st = 128; st > 0; st >>= 1) {
            if (t < st) sm[t] += sm[t + st];
            __syncthreads();
        }
        if (t == 0) g_partial[blk] = sm[0];
        return;
    }

    const int bc = blockIdx.x;
    if (t >= H2 * 7) return;
    const int hp = t / 7;
    const int w8 = t - hp * 7;
    const int h  = hp - 1;
    const bool hv = (unsigned)h < (unsigned)HW;
    const float* xr = x + (size_t)bc * PIX + h * HW;

    __half hb[10];
#pragma unroll
    for (int j = 0; j < 10; j++) {
        int ww = w8 * 8 - 1 + j;
        float v = (hv && (unsigned)ww < (unsigned)HW) ? xr[ww] : 0.f;
        hb[j] = __float2half_rn(v);
    }
    uint32_t p[5];
#pragma unroll
    for (int g = 0; g < 5; g++) {
        __half2 h2 = __halves2half2(hb[2 * g], hb[2 * g + 1]);
        p[g] = *reinterpret_cast<uint32_t*>(&h2);
    }
    uint32_t q[4];
#pragma unroll
    for (int g = 0; g < 4; g++)
        asm("prmt.b32 %0, %1, %2, 0x5432;" : "=r"(q[g]) : "r"(p[g]), "r"(p[g + 1]));

    const size_t base = (size_t)bc * CHW2P + hp * HW + w8 * 8;
    uint4* o0 = reinterpret_cast<uint4*>(g_xh + base);
    uint4* o1 = reinterpret_cast<uint4*>(g_xh + base + (size_t)XCOPY);
    uint4* o2 = reinterpret_cast<uint4*>(g_xh + base + 2 * (size_t)XCOPY);
    *o0 = make_uint4(p[0], p[1], p[2], p[3]);
    *o1 = make_uint4(q[0], q[1], q[2], q[3]);
    *o2 = make_uint4(p[1], p[2], p[3], p[4]);
}

__global__ void absmean_final() {
    __shared__ float sm[256];
    int tid = threadIdx.x;
    sm[tid] = g_partial[tid]; __syncthreads();
    for (int st = 128; st > 0; st >>= 1) {
        if (tid < st) sm[tid] += sm[tid + st];
        __syncthreads();
    }
    if (tid == 0) g_delta = 0.7f * sm[0] / (float)NW;
}

// -------- ternarize + pack into mma-fragment-major fp16 layout -------------
__global__ void ternarize(const float* __restrict__ w) {
    int idx = blockIdx.x * 256 + threadIdx.x;
    float d = g_delta, v = w[idx];
    float t = (v > d) ? 1.f : ((v < -d) ? -1.f : 0.f);
    int co  = idx / KTOT;
    int rem = idx - co * KTOT;
    int ci  = rem / 9;
    int rr  = rem - ci * 9;
    int k   = rr * 256 + ci;
    int s   = k >> 4, kin = k & 15;
    int bm  = co >> 7, m = co & 127, m16 = m >> 4, mi = m & 15;
    int lane = ((mi & 7) << 2) | ((kin >> 1) & 3);
    int aidx = ((kin >> 3) << 1) + (mi >> 3);
    int hp   = kin & 1;
    g_wth[(((size_t)bm * NSTAGE + s) * 8 + m16) * 256 + lane * 8 + aidx * 2 + hp]
        = __float2half_rn(t);
}

// ------------------------------ PTX helpers --------------------------------
__device__ __forceinline__ uint32_t smem_u32(const void* p) {
    uint32_t a;
    asm("{ .reg .u64 t; cvta.to.shared.u64 t, %1; cvt.u32.u64 %0, t; }"
        : "=r"(a) : "l"(p));
    return a;
}
__device__ __forceinline__ void cp16cg(uint32_t dst, const void* src) {
    asm volatile("cp.async.cg.shared.global [%0], [%1], 16;\n" :: "r"(dst), "l"(src));
}
__device__ __forceinline__ void lds128(uint32_t* a, uint32_t addr) {
    asm volatile("ld.shared.v4.b32 {%0,%1,%2,%3}, [%4];"
                 : "=r"(a[0]), "=r"(a[1]), "=r"(a[2]), "=r"(a[3]) : "r"(addr));
}
__device__ __forceinline__ void ldsm4t(uint32_t& b0, uint32_t& b1,
                                       uint32_t& b2, uint32_t& b3, uint32_t addr) {
    asm volatile("ldmatrix.sync.aligned.m8n8.x4.trans.shared.b16 {%0,%1,%2,%3}, [%4];"
                 : "=r"(b0), "=r"(b1), "=r"(b2), "=r"(b3) : "r"(addr));
}
__device__ __forceinline__ void mma16816(float* c, const uint32_t* a,
                                         uint32_t b0, uint32_t b1) {
    asm volatile(
        "mma.sync.aligned.m16n8k16.row.col.f32.f16.f16.f32 "
        "{%0,%1,%2,%3}, {%4,%5,%6,%7}, {%8,%9}, {%0,%1,%2,%3};\n"
        : "+f"(c[0]), "+f"(c[1]), "+f"(c[2]), "+f"(c[3])
        : "r"(a[0]), "r"(a[1]), "r"(a[2]), "r"(a[3]), "r"(b0), "r"(b1));
}
__device__ __forceinline__ void stg64cs(void* p, float x, float y) {
    asm volatile("st.global.cs.v2.f32 [%0], {%1,%2};"
                 :: "l"(p), "f"(x), "f"(y) : "memory");
}

// --------------------------------- main GEMM (persistent) ------------------
__global__ void __launch_bounds__(256, 2)
conv_hmma(const float* __restrict__ alpha, const float* __restrict__ bias,
          float* __restrict__ out)
{
    extern __shared__ char smem[];
    const uint32_t sb0 = smem_u32(smem);
    const int tid  = threadIdx.x;
    const int lane = tid & 31;
    const int warp = tid >> 5;
    const int bm   = blockIdx.x;           // fixed per CTA (TSTEP even)
    int tile = (blockIdx.y << 1) | blockIdx.x;   // 0..295

    // ---- per-CTA fixed producer constants ----
    const int kk = tid >> 4;
    const int c0 = (tid & 15) << 3;
    const uint32_t dstB = (uint32_t)((STG_A + (kk << 8) + (c0 << 1)) ^ ((kk & 7) << 4));
    const uint32_t dstA = (uint32_t)(tid << 4);
    const __half* asrc  = g_wth + (size_t)bm * (NSTAGE * 2048) + tid * 8;

    // B base pointer for a tile index
    auto pbase_of = [&](int t) -> const __half* {
        int bn0 = (t >> 1) * BN;
        int nc  = bn0 + c0;
        int pb  = nc / PIX;
        int pp  = nc - pb * PIX;
        return g_xh + (size_t)(pb * CIN) * CHW2P + pp;
    };

    // ---- per-CTA fixed consumer constants ----
    const uint32_t aoff0 = (uint32_t)((((warp & 3) * 2) << 9) + (lane << 4));
    const uint32_t aoff1 = aoff0 + 512;
    const int t4 = lane >> 3, r = lane & 7;
    const int kt  = (t4 & 1) << 3;
    const int ctb = ((warp >> 2) << 6) + ((t4 >> 1) << 3);
    uint32_t boff[4];
#pragma unroll
    for (int g = 0; g < 4; g++)
        boff[g] = (uint32_t)((STG_A + ((kt + r) << 8) + ((ctb + (g << 4)) << 1))
                             ^ (r << 4));

    const float al = alpha[0];
    const int wm0 = (warp & 3) << 5;
    const int wn0 = (warp >> 2) << 6;
    const int co  = bm * BM + wm0 + (lane >> 2);  // mt=0 row; +16 for mt=1
    const float bi00 = bias[co],      bi08 = bias[co + 8];
    const float bi10 = bias[co + 16], bi18 = bias[co + 24];

    float acc[2][8][4];
#pragma unroll
    for (int i = 0; i < 2; i++)
#pragma unroll
        for (int j = 0; j < 8; j++)
#pragma unroll
            for (int q = 0; q < 4; q++) acc[i][j][q] = 0.f;

    // fill stage t (0..143) of a tile whose B base is pb; slot = t&7
    auto fill = [&](int t, const __half* pb) {
        const uint32_t sb = sb0 + (uint32_t)(t & (D - 1)) * STG_BYTES;
        cp16cg(sb + dstA, asrc + (size_t)t * 2048);
        int ci  = ((t & 15) << 4) + kk;
        int rr  = t >> 4;
        int q   = rr / 3;
        int dwp = rr - q * 3;
        const __half* src = pb + (size_t)dwp * XCOPY
                          + (size_t)ci * CHW2P + q * HW;
        cp16cg(sb + dstB, src);
    };

    const __half* pb_cur  = pbase_of(tile);
    const __half* pb_next = (tile + TSTEP < NTILES) ? pbase_of(tile + TSTEP)
                                                    : pb_cur;

    // ---- prologue: stages 0..D-2 of first tile ----
#pragma unroll
    for (int p = 0; p < D - 1; p++) {
        fill(p, pb_cur);
        asm volatile("cp.async.commit_group;" ::: "memory");
    }

    // ---- persistent tile loop ----
    for (; tile < NTILES; tile += TSTEP) {
        const int bn0 = (tile >> 1) * BN;

#pragma unroll 1
        for (int s = 0; s < NSTAGE; s++) {
            asm volatile("cp.async.wait_group %0;" :: "n"(D - 2) : "memory");
            __syncthreads();             // stage s visible; slot (s-1)%D free
            {
                int tf = s + D - 1;
                if (tf < NSTAGE)               fill(tf, pb_cur);
                else if (tile + TSTEP < NTILES) fill(tf - NSTAGE, pb_next);
            }
            asm volatile("cp.async.commit_group;" ::: "memory");

            const uint32_t st = sb0 + (uint32_t)(s & (D - 1)) * STG_BYTES;
            uint32_t a0[4], a1[4];
            lds128(a0, st + aoff0);
            lds128(a1, st + aoff1);
#pragma unroll
            for (int g = 0; g < 4; g++) {
                uint32_t b0, b1, b2, b3;
                ldsm4t(b0, b1, b2, b3, st + boff[g]);
                mma16816(acc[0][2 * g],     a0, b0, b1);
                mma16816(acc[1][2 * g],     a1, b0, b1);
                mma16816(acc[0][2 * g + 1], a0, b2, b3);
                mma16816(acc[1][2 * g + 1], a1, b2, b3);
            }
        }

        // ---- epilogue for this tile (next tile's prologue is in flight) ----
#pragma unroll
        for (int mt = 0; mt < 2; mt++) {
            int row = co + (mt << 4);
            float biA = mt ? bi10 : bi00;
            float biB = mt ? bi18 : bi08;
#pragma unroll
            for (int nt = 0; nt < 8; nt++) {
                int n = bn0 + wn0 + (nt << 3) + ((lane & 3) << 1);
                int bimg = n / PIX;
                int hw = n - bimg * PIX;
                size_t o = ((size_t)(bimg * COUT + row)) * PIX + hw;
                stg64cs(out + o,           al * acc[mt][nt][0] + biA,
                                           al * acc[mt][nt][1] + biA);
                stg64cs(out + o + 8 * PIX, al * acc[mt][nt][2] + biB,
                                           al * acc[mt][nt][3] + biB);
#pragma unroll
                for (int q = 0; q < 4; q++) acc[mt][nt][q] = 0.f;
            }
        }

        pb_cur = pb_next;
        int t2 = tile + 2 * TSTEP;
        pb_next = (t2 < NTILES) ? pbase_of(t2) : pb_cur;
    }
}

// ------------------------------- launcher -----------------------------------
extern "C" void kernel_launch(void* const* d_in, const int* in_sizes, int n_in,
                              void* d_out, int out_size) {
    const float* x     = (const float*)d_in[0];
    const float* w     = (const float*)d_in[1];
    const float* alpha = (const float*)d_in[2];
    const float* bias  = (const float*)d_in[3];
    float* out = (float*)d_out;

    cudaFuncSetAttribute(conv_hmma, cudaFuncAttributeMaxDynamicSharedMemorySize,
                         SMEM_DYN);

    fused_pre<<<8192 + 256, 416>>>(x, w);   // xtoh || absmean_part
    absmean_final<<<1, 256>>>();
    ternarize<<<NW / 256, 256>>>(w);

    dim3 grid(2, TSTEP / 2);   // 296 persistent CTAs, bm fixed per CTA
    conv_hmma<<<grid, 256, SMEM_DYN>>>(alpha, bias, out);
}